// round 2
// baseline (speedup 1.0000x reference)
#include <cuda_runtime.h>
#include <math.h>

#define LATENT 256
#define HIDDEN 512
#define MAXN   64
#define BATCH  128
#define NPAIR  2016
#define G3     1536
#define NROWS  (MAXN*BATCH)

__device__ float g_seqin[NROWS*2*LATENT];
__device__ float g_X0[NROWS*LATENT];
__device__ float g_gi[NROWS*G3];
__device__ float g_h1[NROWS*HIDDEN];
__device__ float g_h2[NROWS*HIDDEN];
__device__ float g_WhhT0[HIDDEN*G3];
__device__ float g_WhhT1[HIDDEN*G3];
__device__ float g_nodeWT[HIDDEN*HIDDEN];
__device__ float g_Wca[HIDDEN*HIDDEN];
__device__ float g_Wcb[HIDDEN*HIDDEN];
__device__ float g_Am[NROWS*HIDDEN];
__device__ float g_Bm[NROWS*HIDDEN];

typedef unsigned long long u64;

__device__ __forceinline__ u64 pack2(float x, float y) {
    u64 r;
    asm("mov.b64 %0, {%1, %2};" : "=l"(r) : "r"(__float_as_uint(x)), "r"(__float_as_uint(y)));
    return r;
}
__device__ __forceinline__ u64 rep2(float x) { return pack2(x, x); }
__device__ __forceinline__ float2 unpack2(u64 v) {
    unsigned int a, b;
    asm("mov.b64 {%0, %1}, %2;" : "=r"(a), "=r"(b) : "l"(v));
    return make_float2(__uint_as_float(a), __uint_as_float(b));
}
__device__ __forceinline__ u64 ffma2(u64 a, u64 b, u64 c) {
    u64 d;
    asm("fma.rn.f32x2 %0, %1, %2, %3;" : "=l"(d) : "l"(a), "l"(b), "l"(c));
    return d;
}
__device__ __forceinline__ float sigmoidf_(float x) { return 1.0f / (1.0f + expf(-x)); }

__global__ void zero_kernel(float* o, int n) {
    int i = blockIdx.x * 256 + threadIdx.x;
    if (i < n) o[i] = 0.0f;
}

__global__ void transpose_kernel(const float* __restrict__ src, float* __restrict__ dst, int R, int C) {
    __shared__ float tile[32][33];
    int c0 = blockIdx.x * 32, r0 = blockIdx.y * 32;
    int x = threadIdx.x, y = threadIdx.y;
#pragma unroll
    for (int q = 0; q < 32; q += 8)
        tile[y + q][x] = src[(size_t)(r0 + y + q) * C + (c0 + x)];
    __syncthreads();
#pragma unroll
    for (int q = 0; q < 32; q += 8)
        dst[(size_t)(c0 + y + q) * R + (r0 + x)] = tile[x][y + q];
}

__global__ void seqin_kernel(const float* __restrict__ z, const float* __restrict__ pe,
                             const float* __restrict__ emb, float* __restrict__ o) {
    int idx = blockIdx.x * 256 + threadIdx.x;
    int k = idx & 511;
    int b = (idx >> 9) & 127;
    int t = idx >> 16;
    float v;
    if (k < 256) v = z[b * 256 + k] + pe[t * 256 + k];
    else         v = emb[t * 256 + (k - 256)];
    o[idx] = v;
}

// C[r][c] = act(sum_k A[r][k]*W[c][k] + bias[c]); BM=128,BN=64,BK=16; 256 thr; 8x4 per thread via f32x2
__global__ void sgemm_kernel(const float* __restrict__ A, int lda,
                             const float* __restrict__ W, int ldw,
                             const float* __restrict__ bias,
                             float* __restrict__ C,
                             int N, int K,
                             const int* __restrict__ nn, int rowmask) {
    __shared__ float As[16][128];
    __shared__ float Bs[16][64];
    int tid = threadIdx.x;
    int m0 = blockIdx.y * 128, n0 = blockIdx.x * 64;
    int lr = tid >> 2;
    int lk = (tid & 3) << 2;
    int tx = tid & 15, ty = tid >> 4;
    int tn0 = tx << 2, tm0 = ty << 3;

    u64 acc[4][4];
#pragma unroll
    for (int p = 0; p < 4; p++)
#pragma unroll
        for (int n = 0; n < 4; n++) acc[p][n] = 0ULL;

    for (int k0 = 0; k0 < K; k0 += 16) {
        const float* Ap = A + (size_t)(m0 + lr) * lda + k0 + lk;
        float4 av0 = *(const float4*)Ap;
        float4 av1 = *(const float4*)(Ap + (size_t)64 * lda);
        const float* Wp = W + (size_t)(n0 + lr) * ldw + k0 + lk;
        float4 wv = *(const float4*)Wp;
        __syncthreads();
        As[lk + 0][lr] = av0.x; As[lk + 1][lr] = av0.y; As[lk + 2][lr] = av0.z; As[lk + 3][lr] = av0.w;
        As[lk + 0][lr + 64] = av1.x; As[lk + 1][lr + 64] = av1.y; As[lk + 2][lr + 64] = av1.z; As[lk + 3][lr + 64] = av1.w;
        Bs[lk + 0][lr] = wv.x; Bs[lk + 1][lr] = wv.y; Bs[lk + 2][lr] = wv.z; Bs[lk + 3][lr] = wv.w;
        __syncthreads();
#pragma unroll
        for (int kk = 0; kk < 16; kk++) {
            const float* ar = &As[kk][tm0];
            u64 a0 = *(const u64*)(ar + 0);
            u64 a1 = *(const u64*)(ar + 2);
            u64 a2 = *(const u64*)(ar + 4);
            u64 a3 = *(const u64*)(ar + 6);
            float4 bv = *(const float4*)&Bs[kk][tn0];
            u64 rb0 = rep2(bv.x), rb1 = rep2(bv.y), rb2 = rep2(bv.z), rb3 = rep2(bv.w);
            acc[0][0] = ffma2(a0, rb0, acc[0][0]); acc[0][1] = ffma2(a0, rb1, acc[0][1]);
            acc[0][2] = ffma2(a0, rb2, acc[0][2]); acc[0][3] = ffma2(a0, rb3, acc[0][3]);
            acc[1][0] = ffma2(a1, rb0, acc[1][0]); acc[1][1] = ffma2(a1, rb1, acc[1][1]);
            acc[1][2] = ffma2(a1, rb2, acc[1][2]); acc[1][3] = ffma2(a1, rb3, acc[1][3]);
            acc[2][0] = ffma2(a2, rb0, acc[2][0]); acc[2][1] = ffma2(a2, rb1, acc[2][1]);
            acc[2][2] = ffma2(a2, rb2, acc[2][2]); acc[2][3] = ffma2(a2, rb3, acc[2][3]);
            acc[3][0] = ffma2(a3, rb0, acc[3][0]); acc[3][1] = ffma2(a3, rb1, acc[3][1]);
            acc[3][2] = ffma2(a3, rb2, acc[3][2]); acc[3][3] = ffma2(a3, rb3, acc[3][3]);
        }
    }

    bool keep[8];
#pragma unroll
    for (int rr = 0; rr < 8; rr++) {
        if (rowmask) {
            int row = m0 + tm0 + rr;
            keep[rr] = ((row >> 7) < nn[row & 127]);
        } else keep[rr] = true;
    }
#pragma unroll
    for (int n = 0; n < 4; n++) {
        int col = n0 + tn0 + n;
        float bz = bias ? bias[col] : 0.0f;
#pragma unroll
        for (int p = 0; p < 4; p++) {
            float2 v = unpack2(acc[p][n]);
            int rr = 2 * p;
            C[(size_t)(m0 + tm0 + rr) * N + col]     = keep[rr]     ? (v.x + bz) : 0.0f;
            C[(size_t)(m0 + tm0 + rr + 1) * N + col] = keep[rr + 1] ? (v.y + bz) : 0.0f;
        }
    }
}

// one GRU step: grid(16,16), 256 thr = (jq:8, b:8, kh:4); each thread 4 j x 3 gates, 128 k's
__global__ void gru_step_kernel(const float* __restrict__ hprev,
                                const float* __restrict__ gi,
                                const float* __restrict__ WhhT,
                                const float* __restrict__ bhh,
                                float* __restrict__ hout) {
    __shared__ float hs[8 * 512];
    __shared__ float red[3][64][12];
    int tid = threadIdx.x;
    int jq = tid & 7;
    int b  = (tid >> 3) & 7;
    int kh = tid >> 6;
    int j0 = blockIdx.x * 32 + jq * 4;
    int b0 = blockIdx.y * 8;

    if (hprev) {
        const float4* src = (const float4*)(hprev + (size_t)b0 * 512);
        float4* dst = (float4*)hs;
        for (int i = tid; i < 1024; i += 256) dst[i] = src[i];
    }
    __syncthreads();

    u64 ac[3][2];
#pragma unroll
    for (int g = 0; g < 3; g++) { ac[g][0] = 0ULL; ac[g][1] = 0ULL; }

    if (hprev) {
        int kbeg = kh << 7;
#pragma unroll 4
        for (int k = kbeg; k < kbeg + 128; k++) {
            const float* wrow = WhhT + (size_t)k * G3 + j0;
            float4 wr = *(const float4*)(wrow);
            float4 wz = *(const float4*)(wrow + 512);
            float4 wn = *(const float4*)(wrow + 1024);
            u64 hh = rep2(hs[(b << 9) + k]);
            ac[0][0] = ffma2(pack2(wr.x, wr.y), hh, ac[0][0]);
            ac[0][1] = ffma2(pack2(wr.z, wr.w), hh, ac[0][1]);
            ac[1][0] = ffma2(pack2(wz.x, wz.y), hh, ac[1][0]);
            ac[1][1] = ffma2(pack2(wz.z, wz.w), hh, ac[1][1]);
            ac[2][0] = ffma2(pack2(wn.x, wn.y), hh, ac[2][0]);
            ac[2][1] = ffma2(pack2(wn.z, wn.w), hh, ac[2][1]);
        }
    }

    float vals[12];
#pragma unroll
    for (int g = 0; g < 3; g++) {
        float2 lo = unpack2(ac[g][0]);
        float2 hi = unpack2(ac[g][1]);
        vals[g * 4 + 0] = lo.x; vals[g * 4 + 1] = lo.y;
        vals[g * 4 + 2] = hi.x; vals[g * 4 + 3] = hi.y;
    }
    int slot = b * 8 + jq;
    if (kh != 0) {
#pragma unroll
        for (int x = 0; x < 12; x++) red[kh - 1][slot][x] = vals[x];
    }
    __syncthreads();
    if (kh == 0) {
#pragma unroll
        for (int s = 0; s < 3; s++)
#pragma unroll
            for (int x = 0; x < 12; x++) vals[x] += red[s][slot][x];

        const float* gib = gi + (size_t)(b0 + b) * G3;
        float* hob = hout + (size_t)(b0 + b) * 512;
#pragma unroll
        for (int jj = 0; jj < 4; jj++) {
            int j = j0 + jj;
            float gr = vals[0 + jj] + bhh[j];
            float gz = vals[4 + jj] + bhh[512 + j];
            float gn = vals[8 + jj] + bhh[1024 + j];
            float r  = sigmoidf_(gib[j] + gr);
            float zg = sigmoidf_(gib[512 + j] + gz);
            float n  = tanhf(gib[1024 + j] + r * gn);
            float hold = hprev ? hs[(b << 9) + j] : 0.0f;
            hob[j] = (1.0f - zg) * n + zg * hold;
        }
    }
}

__global__ void pair_kernel(const float* __restrict__ Am, const float* __restrict__ Bm,
                            const float* __restrict__ b1, const float* __restrict__ W2,
                            const float* __restrict__ b2, const float* __restrict__ gu,
                            const int* __restrict__ nn, float* __restrict__ out) {
    int tid = threadIdx.x;
    int warp = tid >> 5, lane = tid & 31;
    int p = blockIdx.x * 8 + warp;
    int bb = blockIdx.y;

    int i = (int)((127.0f - sqrtf((float)(16129 - 8 * p))) * 0.5f);
    if (i < 0) i = 0; if (i > 62) i = 62;
    while (i > 0 && ((i * (127 - i)) >> 1) > p) i--;
    while (i < 62 && (((i + 1) * (126 - i)) >> 1) <= p) i++;
    int j = i + 1 + (p - ((i * (127 - i)) >> 1));

    const float4* Ar = (const float4*)(Am + ((size_t)i * 128 + bb) * 512);
    const float4* Br = (const float4*)(Bm + ((size_t)j * 128 + bb) * 512);
    const float4* bi4 = (const float4*)b1;
    const float4* w04 = (const float4*)W2;
    const float4* w14 = (const float4*)(W2 + 512);

    float p0 = 0.0f, p1 = 0.0f;
#pragma unroll
    for (int q = 0; q < 4; q++) {
        int c = q * 32 + lane;
        float4 a = Ar[c], bv = Br[c], bi = bi4[c], w0 = w04[c], w1 = w14[c];
        float h0 = fmaxf(a.x + bv.x + bi.x, 0.0f);
        float h1 = fmaxf(a.y + bv.y + bi.y, 0.0f);
        float h2 = fmaxf(a.z + bv.z + bi.z, 0.0f);
        float h3 = fmaxf(a.w + bv.w + bi.w, 0.0f);
        p0 += h0 * w0.x + h1 * w0.y + h2 * w0.z + h3 * w0.w;
        p1 += h0 * w1.x + h1 * w1.y + h2 * w1.z + h3 * w1.w;
    }
#pragma unroll
    for (int o = 16; o > 0; o >>= 1) {
        p0 += __shfl_xor_sync(0xffffffffu, p0, o);
        p1 += __shfl_xor_sync(0xffffffffu, p1, o);
    }
    if (lane == 0 && j < nn[bb]) {
        float l0 = p0 + b2[0];
        float l1 = p1 + b2[1];
        const float* up = gu + ((size_t)bb * NPAIR + p) * 2;
        float g0 = -logf(-logf(up[0] + 1e-10f) + 1e-10f);
        float g1 = -logf(-logf(up[1] + 1e-10f) + 1e-10f);
        float val = (l0 + g0 >= l1 + g1) ? 1.0f : 0.0f;
        out[(size_t)bb * 4096 + i * 64 + j] = val;
        out[(size_t)bb * 4096 + j * 64 + i] = val;
    }
}

extern "C" void kernel_launch(void* const* d_in, const int* in_sizes, int n_in,
                              void* d_out, int out_size) {
    int off = (n_in >= 21) ? 1 : 0;
    const float* z      = (const float*)d_in[0];
    const int*   nn     = (const int*)  d_in[1];
    const float* gu     = (const float*)d_in[2 + off];
    const float* emb    = (const float*)d_in[3 + off];
    const float* pe     = (const float*)d_in[4 + off];
    const float* W_pre  = (const float*)d_in[5 + off];
    const float* b_pre  = (const float*)d_in[6 + off];
    const float* Wih0   = (const float*)d_in[7 + off];
    const float* Whh0   = (const float*)d_in[8 + off];
    const float* bih0   = (const float*)d_in[9 + off];
    const float* bhh0   = (const float*)d_in[10 + off];
    const float* Wih1   = (const float*)d_in[11 + off];
    const float* Whh1   = (const float*)d_in[12 + off];
    const float* bih1   = (const float*)d_in[13 + off];
    const float* bhh1   = (const float*)d_in[14 + off];
    const float* node_W = (const float*)d_in[15 + off];
    const float* adj_W1 = (const float*)d_in[16 + off];
    const float* adj_b1 = (const float*)d_in[17 + off];
    const float* adj_W2 = (const float*)d_in[18 + off];
    const float* adj_b2 = (const float*)d_in[19 + off];
    float* out = (float*)d_out;

    float *seqin, *X0, *gi, *h1, *h2, *WhhT0, *WhhT1, *nodeWT, *Wca, *Wcb, *Am, *Bm;
    cudaGetSymbolAddress((void**)&seqin, g_seqin);
    cudaGetSymbolAddress((void**)&X0, g_X0);
    cudaGetSymbolAddress((void**)&gi, g_gi);
    cudaGetSymbolAddress((void**)&h1, g_h1);
    cudaGetSymbolAddress((void**)&h2, g_h2);
    cudaGetSymbolAddress((void**)&WhhT0, g_WhhT0);
    cudaGetSymbolAddress((void**)&WhhT1, g_WhhT1);
    cudaGetSymbolAddress((void**)&nodeWT, g_nodeWT);
    cudaGetSymbolAddress((void**)&Wca, g_Wca);
    cudaGetSymbolAddress((void**)&Wcb, g_Wcb);
    cudaGetSymbolAddress((void**)&Am, g_Am);
    cudaGetSymbolAddress((void**)&Bm, g_Bm);

    // zero output
    zero_kernel<<<(out_size + 255) / 256, 256>>>(out, out_size);

    // weight preprocessing (parallel, each call)
    transpose_kernel<<<dim3(512 / 32, 1536 / 32), dim3(32, 8)>>>(Whh0, WhhT0, 1536, 512);
    transpose_kernel<<<dim3(512 / 32, 1536 / 32), dim3(32, 8)>>>(Whh1, WhhT1, 1536, 512);
    transpose_kernel<<<dim3(512 / 32, 512 / 32), dim3(32, 8)>>>(node_W, nodeWT, 512, 512);
    // Wca = W1a @ node_W  (Wca[h][k] = sum_m adj_W1[h][m] * nodeWT[k][m])
    sgemm_kernel<<<dim3(8, 4), 256>>>(adj_W1, 1024, nodeWT, 512, nullptr, Wca, 512, 512, nullptr, 0);
    sgemm_kernel<<<dim3(8, 4), 256>>>(adj_W1 + 512, 1024, nodeWT, 512, nullptr, Wcb, 512, 512, nullptr, 0);

    // build seq input, pre-linear (masked)
    seqin_kernel<<<NROWS * 512 / 256, 256>>>(z, pe, emb, seqin);
    sgemm_kernel<<<dim3(4, 64), 256>>>(seqin, 512, W_pre, 512, b_pre, X0, 256, 512, nn, 1);

    // layer 0
    sgemm_kernel<<<dim3(24, 64), 256>>>(X0, 256, Wih0, 256, bih0, gi, 1536, 256, nullptr, 0);
    for (int t = 0; t < MAXN; t++) {
        const float* hp = (t == 0) ? nullptr : (h1 + (size_t)(t - 1) * 128 * 512);
        gru_step_kernel<<<dim3(16, 16), 256>>>(hp, gi + (size_t)t * 128 * G3, WhhT0, bhh0,
                                               h1 + (size_t)t * 128 * 512);
    }

    // layer 1
    sgemm_kernel<<<dim3(24, 64), 256>>>(h1, 512, Wih1, 512, bih1, gi, 1536, 512, nullptr, 0);
    for (int t = 0; t < MAXN; t++) {
        const float* hp = (t == 0) ? nullptr : (h2 + (size_t)(t - 1) * 128 * 512);
        gru_step_kernel<<<dim3(16, 16), 256>>>(hp, gi + (size_t)t * 128 * G3, WhhT1, bhh1,
                                               h2 + (size_t)t * 128 * 512);
    }

    // A/B projections with folded node_W + adj_W1 halves
    sgemm_kernel<<<dim3(8, 64), 256>>>(h2, 512, Wca, 512, nullptr, Am, 512, 512, nullptr, 0);
    sgemm_kernel<<<dim3(8, 64), 256>>>(h2, 512, Wcb, 512, nullptr, Bm, 512, 512, nullptr, 0);

    // pairwise logits + gumbel argmax -> adjacency
    pair_kernel<<<dim3(NPAIR / 8, BATCH), 256>>>(Am, Bm, adj_b1, adj_W2, adj_b2, gu, nn, out);
}

// round 3
// speedup vs baseline: 1.8380x; 1.8380x over previous
#include <cuda_runtime.h>
#include <math.h>

#define LATENT 256
#define HIDDEN 512
#define MAXN   64
#define BATCH  128
#define NPAIR  2016
#define G3     1536
#define NROWS  (MAXN*BATCH)

__device__ float g_seqin[NROWS*2*LATENT];
__device__ float g_X0[NROWS*LATENT];
__device__ float g_gi[NROWS*G3];
__device__ float g_h1[NROWS*HIDDEN];
__device__ float g_h2[NROWS*HIDDEN];
__device__ float g_WhhT0[HIDDEN*G3];
__device__ float g_WhhT1[HIDDEN*G3];
__device__ float g_nodeWT[HIDDEN*HIDDEN];
__device__ float g_Wca[HIDDEN*HIDDEN];
__device__ float g_Wcb[HIDDEN*HIDDEN];
__device__ float g_Am[NROWS*HIDDEN];
__device__ float g_Bm[NROWS*HIDDEN];
__device__ int   g_cnt;

typedef unsigned long long u64;

__device__ __forceinline__ u64 pack2(float x, float y) {
    u64 r;
    asm("mov.b64 %0, {%1, %2};" : "=l"(r) : "r"(__float_as_uint(x)), "r"(__float_as_uint(y)));
    return r;
}
__device__ __forceinline__ u64 rep2(float x) { return pack2(x, x); }
__device__ __forceinline__ float2 unpack2(u64 v) {
    unsigned int a, b;
    asm("mov.b64 {%0, %1}, %2;" : "=r"(a), "=r"(b) : "l"(v));
    return make_float2(__uint_as_float(a), __uint_as_float(b));
}
__device__ __forceinline__ u64 ffma2(u64 a, u64 b, u64 c) {
    u64 d;
    asm("fma.rn.f32x2 %0, %1, %2, %3;" : "=l"(d) : "l"(a), "l"(b), "l"(c));
    return d;
}
__device__ __forceinline__ float sigmoidf_(float x) { return 1.0f / (1.0f + expf(-x)); }

__global__ void zero_kernel(float* o, int n) {
    int i = blockIdx.x * 256 + threadIdx.x;
    if (i < n) o[i] = 0.0f;
}

__global__ void transpose_kernel(const float* __restrict__ src, float* __restrict__ dst, int R, int C) {
    __shared__ float tile[32][33];
    int c0 = blockIdx.x * 32, r0 = blockIdx.y * 32;
    int x = threadIdx.x, y = threadIdx.y;
#pragma unroll
    for (int q = 0; q < 32; q += 8)
        tile[y + q][x] = src[(size_t)(r0 + y + q) * C + (c0 + x)];
    __syncthreads();
#pragma unroll
    for (int q = 0; q < 32; q += 8)
        dst[(size_t)(c0 + y + q) * R + (r0 + x)] = tile[x][y + q];
}

__global__ void seqin_kernel(const float* __restrict__ z, const float* __restrict__ pe,
                             const float* __restrict__ emb, float* __restrict__ o) {
    int idx = blockIdx.x * 256 + threadIdx.x;
    int k = idx & 511;
    int b = (idx >> 9) & 127;
    int t = idx >> 16;
    float v;
    if (k < 256) v = z[b * 256 + k] + pe[t * 256 + k];
    else         v = emb[t * 256 + (k - 256)];
    o[idx] = v;
}

// C[r][c] = sum_k A[r][k]*W[c][k] (+bias); BM=128,BN=64,BK=16; 256 thr; 8x4 per thread via f32x2
__global__ void sgemm_kernel(const float* __restrict__ A, int lda,
                             const float* __restrict__ W, int ldw,
                             const float* __restrict__ bias,
                             float* __restrict__ C,
                             int N, int K,
                             const int* __restrict__ nn, int rowmask) {
    __shared__ float As[16][128];
    __shared__ float Bs[16][64];
    int tid = threadIdx.x;
    int m0 = blockIdx.y * 128, n0 = blockIdx.x * 64;
    int lr = tid >> 2;
    int lk = (tid & 3) << 2;
    int tx = tid & 15, ty = tid >> 4;
    int tn0 = tx << 2, tm0 = ty << 3;

    u64 acc[4][4];
#pragma unroll
    for (int p = 0; p < 4; p++)
#pragma unroll
        for (int n = 0; n < 4; n++) acc[p][n] = 0ULL;

    for (int k0 = 0; k0 < K; k0 += 16) {
        const float* Ap = A + (size_t)(m0 + lr) * lda + k0 + lk;
        float4 av0 = *(const float4*)Ap;
        float4 av1 = *(const float4*)(Ap + (size_t)64 * lda);
        const float* Wp = W + (size_t)(n0 + lr) * ldw + k0 + lk;
        float4 wv = *(const float4*)Wp;
        __syncthreads();
        As[lk + 0][lr] = av0.x; As[lk + 1][lr] = av0.y; As[lk + 2][lr] = av0.z; As[lk + 3][lr] = av0.w;
        As[lk + 0][lr + 64] = av1.x; As[lk + 1][lr + 64] = av1.y; As[lk + 2][lr + 64] = av1.z; As[lk + 3][lr + 64] = av1.w;
        Bs[lk + 0][lr] = wv.x; Bs[lk + 1][lr] = wv.y; Bs[lk + 2][lr] = wv.z; Bs[lk + 3][lr] = wv.w;
        __syncthreads();
#pragma unroll
        for (int kk = 0; kk < 16; kk++) {
            const u64* ar = (const u64*)&As[kk][tm0];
            u64 a0 = ar[0], a1 = ar[1], a2 = ar[2], a3 = ar[3];
            float4 bv = *(const float4*)&Bs[kk][tn0];
            u64 rb0 = rep2(bv.x), rb1 = rep2(bv.y), rb2 = rep2(bv.z), rb3 = rep2(bv.w);
            acc[0][0] = ffma2(a0, rb0, acc[0][0]); acc[0][1] = ffma2(a0, rb1, acc[0][1]);
            acc[0][2] = ffma2(a0, rb2, acc[0][2]); acc[0][3] = ffma2(a0, rb3, acc[0][3]);
            acc[1][0] = ffma2(a1, rb0, acc[1][0]); acc[1][1] = ffma2(a1, rb1, acc[1][1]);
            acc[1][2] = ffma2(a1, rb2, acc[1][2]); acc[1][3] = ffma2(a1, rb3, acc[1][3]);
            acc[2][0] = ffma2(a2, rb0, acc[2][0]); acc[2][1] = ffma2(a2, rb1, acc[2][1]);
            acc[2][2] = ffma2(a2, rb2, acc[2][2]); acc[2][3] = ffma2(a2, rb3, acc[2][3]);
            acc[3][0] = ffma2(a3, rb0, acc[3][0]); acc[3][1] = ffma2(a3, rb1, acc[3][1]);
            acc[3][2] = ffma2(a3, rb2, acc[3][2]); acc[3][3] = ffma2(a3, rb3, acc[3][3]);
        }
    }

    bool keep[8];
#pragma unroll
    for (int rr = 0; rr < 8; rr++) {
        if (rowmask) {
            int row = m0 + tm0 + rr;
            keep[rr] = ((row >> 7) < nn[row & 127]);
        } else keep[rr] = true;
    }
#pragma unroll
    for (int n = 0; n < 4; n++) {
        int col = n0 + tn0 + n;
        float bz = bias ? bias[col] : 0.0f;
#pragma unroll
        for (int p = 0; p < 4; p++) {
            float2 v = unpack2(acc[p][n]);
            int rr = 2 * p;
            C[(size_t)(m0 + tm0 + rr) * N + col]     = keep[rr]     ? (v.x + bz) : 0.0f;
            C[(size_t)(m0 + tm0 + rr + 1) * N + col] = keep[rr + 1] ? (v.y + bz) : 0.0f;
        }
    }
}

// ---------- persistent GRU layer: 128 CTAs (all resident), 64 steps, W in smem ----------
#define WS_ELE   (512*48)
#define HS_ELE   (512*36)
#define SMEM_GRU ((WS_ELE + HS_ELE)*4 + 8*32*24*8)

__global__ void __launch_bounds__(256, 1) gru_layer_kernel(
    const float* __restrict__ gi, const float* __restrict__ WhhT,
    const float* __restrict__ bhh, float* __restrict__ hout,
    int gen_base, int* cnt)
{
    extern __shared__ float sm[];
    float* ws  = sm;                    // [k][g*16+jj]  512*48
    float* hsm = sm + WS_ELE;           // [k][36] (cols 0..31 = local b)
    u64*   red = (u64*)(sm + WS_ELE + HS_ELE);   // [8][32][24]

    int tid = threadIdx.x;
    int jb = blockIdx.x & 31, mb = blockIdx.x >> 5;
    int j0 = jb * 16, b0 = mb * 32;

    for (int idx = tid; idx < WS_ELE; idx += 256) {
        int k = idx / 48, c = idx - k * 48;
        int g = c >> 4, jj = c & 15;
        ws[idx] = WhhT[(size_t)k * G3 + g * 512 + j0 + jj];
    }
    for (int idx = tid; idx < HS_ELE; idx += 256) hsm[idx] = 0.0f;
    __syncthreads();

    int warp = tid >> 5, lane = tid & 31;
    int bg = lane & 7, jg = lane >> 3;
    int tile = jg * 8 + bg;
    int kbeg = warp << 6;

    // pointwise-thread mapping
    int ptile = tid >> 3;
    int pi = (tid >> 1) & 3;
    int pp = tid & 1;
    int pbg = ptile & 7, pjg = ptile >> 3;
    int pbb = pbg * 4 + pi;
    int pjl = pjg * 4 + 2 * pp;

    for (int t = 0; t < MAXN; t++) {
        if (t > 0) {
            const float* hp = hout + ((size_t)(t - 1) * 128 + b0) * 512 + (size_t)lane * 512;
            for (int k4 = warp; k4 < 128; k4 += 8) {
                float4 v = __ldcg((const float4*)(hp + k4 * 4));
                int k = k4 * 4;
                hsm[(k + 0) * 36 + lane] = v.x;
                hsm[(k + 1) * 36 + lane] = v.y;
                hsm[(k + 2) * 36 + lane] = v.z;
                hsm[(k + 3) * 36 + lane] = v.w;
            }
        }
        __syncthreads();

        u64 acc[4][6];
#pragma unroll
        for (int i = 0; i < 4; i++)
#pragma unroll
            for (int n = 0; n < 6; n++) acc[i][n] = 0ULL;

        if (t > 0) {
            const float* wbase = ws + jg * 4;
            const float* hbase = hsm + bg * 4;
#pragma unroll 2
            for (int k = kbeg; k < kbeg + 64; k++) {
                const float* wr = wbase + k * 48;
                ulonglong2 w0 = *(const ulonglong2*)(wr);
                ulonglong2 w1 = *(const ulonglong2*)(wr + 16);
                ulonglong2 w2 = *(const ulonglong2*)(wr + 32);
                float4 hv = *(const float4*)(hbase + k * 36);
                u64 h0 = rep2(hv.x), h1 = rep2(hv.y), h2 = rep2(hv.z), h3 = rep2(hv.w);
                acc[0][0] = ffma2(w0.x, h0, acc[0][0]); acc[0][1] = ffma2(w0.y, h0, acc[0][1]);
                acc[0][2] = ffma2(w1.x, h0, acc[0][2]); acc[0][3] = ffma2(w1.y, h0, acc[0][3]);
                acc[0][4] = ffma2(w2.x, h0, acc[0][4]); acc[0][5] = ffma2(w2.y, h0, acc[0][5]);
                acc[1][0] = ffma2(w0.x, h1, acc[1][0]); acc[1][1] = ffma2(w0.y, h1, acc[1][1]);
                acc[1][2] = ffma2(w1.x, h1, acc[1][2]); acc[1][3] = ffma2(w1.y, h1, acc[1][3]);
                acc[1][4] = ffma2(w2.x, h1, acc[1][4]); acc[1][5] = ffma2(w2.y, h1, acc[1][5]);
                acc[2][0] = ffma2(w0.x, h2, acc[2][0]); acc[2][1] = ffma2(w0.y, h2, acc[2][1]);
                acc[2][2] = ffma2(w1.x, h2, acc[2][2]); acc[2][3] = ffma2(w1.y, h2, acc[2][3]);
                acc[2][4] = ffma2(w2.x, h2, acc[2][4]); acc[2][5] = ffma2(w2.y, h2, acc[2][5]);
                acc[3][0] = ffma2(w0.x, h3, acc[3][0]); acc[3][1] = ffma2(w0.y, h3, acc[3][1]);
                acc[3][2] = ffma2(w1.x, h3, acc[3][2]); acc[3][3] = ffma2(w1.y, h3, acc[3][3]);
                acc[3][4] = ffma2(w2.x, h3, acc[3][4]); acc[3][5] = ffma2(w2.y, h3, acc[3][5]);
            }
        }

        u64* rd = red + ((size_t)warp * 32 + tile) * 24;
#pragma unroll
        for (int i = 0; i < 4; i++)
#pragma unroll
            for (int n = 0; n < 6; n++) rd[i * 6 + n] = acc[i][n];
        __syncthreads();

        // reduce 8 k-splits + GRU pointwise (each thread: 1 b, 2 consecutive j)
        {
            float2 s[3];
#pragma unroll
            for (int g = 0; g < 3; g++) { s[g].x = 0.0f; s[g].y = 0.0f; }
#pragma unroll
            for (int sp = 0; sp < 8; sp++) {
                const u64* rr = red + ((size_t)sp * 32 + ptile) * 24 + pi * 6;
#pragma unroll
                for (int g = 0; g < 3; g++) {
                    float2 v = unpack2(rr[g * 2 + pp]);
                    s[g].x += v.x; s[g].y += v.y;
                }
            }
            int b = b0 + pbb;
            int j = j0 + pjl;
            const float* gb = gi + ((size_t)t * 128 + b) * G3;
            float2 gir = *(const float2*)(gb + j);
            float2 giz = *(const float2*)(gb + 512 + j);
            float2 gin = *(const float2*)(gb + 1024 + j);
            float2 br  = *(const float2*)(bhh + j);
            float2 bz  = *(const float2*)(bhh + 512 + j);
            float2 bn  = *(const float2*)(bhh + 1024 + j);
            float ho0 = hsm[(j + 0) * 36 + pbb];
            float ho1 = hsm[(j + 1) * 36 + pbb];

            float r0 = sigmoidf_(gir.x + s[0].x + br.x);
            float r1 = sigmoidf_(gir.y + s[0].y + br.y);
            float z0 = sigmoidf_(giz.x + s[1].x + bz.x);
            float z1 = sigmoidf_(giz.y + s[1].y + bz.y);
            float n0 = tanhf(gin.x + r0 * (s[2].x + bn.x));
            float n1 = tanhf(gin.y + r1 * (s[2].y + bn.y));
            float2 hv;
            hv.x = (1.0f - z0) * n0 + z0 * ho0;
            hv.y = (1.0f - z1) * n1 + z1 * ho1;
            *(float2*)(hout + ((size_t)t * 128 + b) * 512 + j) = hv;
        }

        if (t < MAXN - 1) {
            __syncthreads();
            if (tid == 0) {
                __threadfence();
                atomicAdd(cnt, 1);
                int target = 128 * (gen_base + t + 1);
                volatile int* vc = (volatile int*)cnt;
                while (*vc < target) __nanosleep(64);
                __threadfence();
            }
            __syncthreads();
        }
    }
}

__global__ void pair_kernel(const float* __restrict__ Am, const float* __restrict__ Bm,
                            const float* __restrict__ b1, const float* __restrict__ W2,
                            const float* __restrict__ b2, const float* __restrict__ gu,
                            const int* __restrict__ nn, float* __restrict__ out) {
    int tid = threadIdx.x;
    int warp = tid >> 5, lane = tid & 31;
    int p = blockIdx.x * 8 + warp;
    int bb = blockIdx.y;

    int i = (int)((127.0f - sqrtf((float)(16129 - 8 * p))) * 0.5f);
    if (i < 0) i = 0; if (i > 62) i = 62;
    while (i > 0 && ((i * (127 - i)) >> 1) > p) i--;
    while (i < 62 && (((i + 1) * (126 - i)) >> 1) <= p) i++;
    int j = i + 1 + (p - ((i * (127 - i)) >> 1));

    const float4* Ar = (const float4*)(Am + ((size_t)i * 128 + bb) * 512);
    const float4* Br = (const float4*)(Bm + ((size_t)j * 128 + bb) * 512);
    const float4* bi4 = (const float4*)b1;
    const float4* w04 = (const float4*)W2;
    const float4* w14 = (const float4*)(W2 + 512);

    float p0 = 0.0f, p1 = 0.0f;
#pragma unroll
    for (int q = 0; q < 4; q++) {
        int c = q * 32 + lane;
        float4 a = Ar[c], bv = Br[c], bi = bi4[c], w0 = w04[c], w1 = w14[c];
        float h0 = fmaxf(a.x + bv.x + bi.x, 0.0f);
        float h1 = fmaxf(a.y + bv.y + bi.y, 0.0f);
        float h2 = fmaxf(a.z + bv.z + bi.z, 0.0f);
        float h3 = fmaxf(a.w + bv.w + bi.w, 0.0f);
        p0 += h0 * w0.x + h1 * w0.y + h2 * w0.z + h3 * w0.w;
        p1 += h0 * w1.x + h1 * w1.y + h2 * w1.z + h3 * w1.w;
    }
#pragma unroll
    for (int o = 16; o > 0; o >>= 1) {
        p0 += __shfl_xor_sync(0xffffffffu, p0, o);
        p1 += __shfl_xor_sync(0xffffffffu, p1, o);
    }
    if (lane == 0 && j < nn[bb]) {
        float l0 = p0 + b2[0];
        float l1 = p1 + b2[1];
        const float* up = gu + ((size_t)bb * NPAIR + p) * 2;
        float g0 = -logf(-logf(up[0] + 1e-10f) + 1e-10f);
        float g1 = -logf(-logf(up[1] + 1e-10f) + 1e-10f);
        float val = (l0 + g0 >= l1 + g1) ? 1.0f : 0.0f;
        out[(size_t)bb * 4096 + i * 64 + j] = val;
        out[(size_t)bb * 4096 + j * 64 + i] = val;
    }
}

extern "C" void kernel_launch(void* const* d_in, const int* in_sizes, int n_in,
                              void* d_out, int out_size) {
    int off = (n_in >= 21) ? 1 : 0;
    const float* z      = (const float*)d_in[0];
    const int*   nn     = (const int*)  d_in[1];
    const float* gu     = (const float*)d_in[2 + off];
    const float* emb    = (const float*)d_in[3 + off];
    const float* pe     = (const float*)d_in[4 + off];
    const float* W_pre  = (const float*)d_in[5 + off];
    const float* b_pre  = (const float*)d_in[6 + off];
    const float* Wih0   = (const float*)d_in[7 + off];
    const float* Whh0   = (const float*)d_in[8 + off];
    const float* bih0   = (const float*)d_in[9 + off];
    const float* bhh0   = (const float*)d_in[10 + off];
    const float* Wih1   = (const float*)d_in[11 + off];
    const float* Whh1   = (const float*)d_in[12 + off];
    const float* bih1   = (const float*)d_in[13 + off];
    const float* bhh1   = (const float*)d_in[14 + off];
    const float* node_W = (const float*)d_in[15 + off];
    const float* adj_W1 = (const float*)d_in[16 + off];
    const float* adj_b1 = (const float*)d_in[17 + off];
    const float* adj_W2 = (const float*)d_in[18 + off];
    const float* adj_b2 = (const float*)d_in[19 + off];
    float* out = (float*)d_out;

    float *seqin, *X0, *gi, *h1, *h2, *WhhT0, *WhhT1, *nodeWT, *Wca, *Wcb, *Am, *Bm;
    int* cnt;
    cudaGetSymbolAddress((void**)&seqin, g_seqin);
    cudaGetSymbolAddress((void**)&X0, g_X0);
    cudaGetSymbolAddress((void**)&gi, g_gi);
    cudaGetSymbolAddress((void**)&h1, g_h1);
    cudaGetSymbolAddress((void**)&h2, g_h2);
    cudaGetSymbolAddress((void**)&WhhT0, g_WhhT0);
    cudaGetSymbolAddress((void**)&WhhT1, g_WhhT1);
    cudaGetSymbolAddress((void**)&nodeWT, g_nodeWT);
    cudaGetSymbolAddress((void**)&Wca, g_Wca);
    cudaGetSymbolAddress((void**)&Wcb, g_Wcb);
    cudaGetSymbolAddress((void**)&Am, g_Am);
    cudaGetSymbolAddress((void**)&Bm, g_Bm);
    cudaGetSymbolAddress((void**)&cnt, g_cnt);

    static int smem_set = 0;
    if (!smem_set) {
        cudaFuncSetAttribute(gru_layer_kernel, cudaFuncAttributeMaxDynamicSharedMemorySize, SMEM_GRU);
        smem_set = 1;
    }

    cudaMemsetAsync(cnt, 0, sizeof(int));
    zero_kernel<<<(out_size + 255) / 256, 256>>>(out, out_size);

    transpose_kernel<<<dim3(512 / 32, 1536 / 32), dim3(32, 8)>>>(Whh0, WhhT0, 1536, 512);
    transpose_kernel<<<dim3(512 / 32, 1536 / 32), dim3(32, 8)>>>(Whh1, WhhT1, 1536, 512);
    transpose_kernel<<<dim3(512 / 32, 512 / 32), dim3(32, 8)>>>(node_W, nodeWT, 512, 512);
    sgemm_kernel<<<dim3(8, 4), 256>>>(adj_W1, 1024, nodeWT, 512, nullptr, Wca, 512, 512, nullptr, 0);
    sgemm_kernel<<<dim3(8, 4), 256>>>(adj_W1 + 512, 1024, nodeWT, 512, nullptr, Wcb, 512, 512, nullptr, 0);

    seqin_kernel<<<NROWS * 512 / 256, 256>>>(z, pe, emb, seqin);
    sgemm_kernel<<<dim3(4, 64), 256>>>(seqin, 512, W_pre, 512, b_pre, X0, 256, 512, nn, 1);

    // layer 0
    sgemm_kernel<<<dim3(24, 64), 256>>>(X0, 256, Wih0, 256, bih0, gi, 1536, 256, nullptr, 0);
    gru_layer_kernel<<<128, 256, SMEM_GRU>>>(gi, WhhT0, bhh0, h1, 0, cnt);

    // layer 1
    sgemm_kernel<<<dim3(24, 64), 256>>>(h1, 512, Wih1, 512, bih1, gi, 1536, 512, nullptr, 0);
    gru_layer_kernel<<<128, 256, SMEM_GRU>>>(gi, WhhT1, bhh1, h2, 63, cnt);

    // A/B projections with folded node_W + adj_W1 halves
    sgemm_kernel<<<dim3(8, 64), 256>>>(h2, 512, Wca, 512, nullptr, Am, 512, 512, nullptr, 0);
    sgemm_kernel<<<dim3(8, 64), 256>>>(h2, 512, Wcb, 512, nullptr, Bm, 512, 512, nullptr, 0);

    pair_kernel<<<dim3(NPAIR / 8, BATCH), 256>>>(Am, Bm, adj_b1, adj_W2, adj_b2, gu, nn, out);
}